// round 7
// baseline (speedup 1.0000x reference)
#include <cuda_runtime.h>
#include <cuda_bf16.h>

#define N_NODES_MAX 50000
#define N_EDGES_MAX 1600000
#define IN_DIM 128
#define OUT_DIM 32
#define N_HEADS 4
#define WH_COLS (N_HEADS * OUT_DIM)   // 128

// ---------------- scratch (static device memory; no allocs) ----------------
__device__ __align__(16) float g_Wh[N_NODES_MAX * WH_COLS];        // 25.6 MB
__device__ __align__(16) float g_ssrc[N_NODES_MAX * N_HEADS];      // 0.8 MB
__device__ __align__(16) float g_sdst[N_NODES_MAX * N_HEADS];      // 0.8 MB
__device__ __align__(16) float g_max[N_NODES_MAX * N_HEADS];
__device__ __align__(16) float g_sum[N_NODES_MAX * N_HEADS];
__device__ int   g_deg[N_NODES_MAX];
__device__ int   g_off[N_NODES_MAX + 1];
__device__ int   g_cur[N_NODES_MAX];
__device__ int   g_csr_src[N_EDGES_MAX];                           // 6.4 MB

// ---------------- K0: zero degree histogram ----------------
__global__ void k_zero(int n_nodes) {
    int i = blockIdx.x * blockDim.x + threadIdx.x;
    if (i < n_nodes) g_deg[i] = 0;
}

// ---------------- K1: Wh = x @ W  (fused 128x128 GEMM) ----------
// weight[h][i][o] viewed as Wcat[i][h*32+o]; 64KB -> L1-resident.
// x tile (32 rows) staged in smem. Each thread computes a 4x4 register tile.
__global__ void __launch_bounds__(256) k_wh(const float* __restrict__ x,
                                            const float* __restrict__ w,
                                            int n_nodes) {
    __shared__ float xs[32 * IN_DIM];   // 16 KB
    int tid  = threadIdx.x;
    int row0 = blockIdx.x * 32;

    for (int idx = tid; idx < 32 * IN_DIM; idx += 256) {
        int r = idx >> 7, i = idx & 127;
        int n = row0 + r;
        xs[idx] = (n < n_nodes) ? x[(size_t)n * IN_DIM + i] : 0.f;
    }
    __syncthreads();

    int tx = tid & 31;   // col group: cols [4*tx, 4*tx+4)
    int ty = tid >> 5;   // row group: rows [4*ty, 4*ty+4)

    int c = tx * 4;
    int h = c >> 5, o = c & 31;   // 4 consecutive cols stay within one head

    float acc[4][4] = {};
    #pragma unroll 4
    for (int i = 0; i < IN_DIM; i++) {
        float wv0 = w[(size_t)h * (IN_DIM * OUT_DIM) + i * OUT_DIM + o + 0];
        float wv1 = w[(size_t)h * (IN_DIM * OUT_DIM) + i * OUT_DIM + o + 1];
        float wv2 = w[(size_t)h * (IN_DIM * OUT_DIM) + i * OUT_DIM + o + 2];
        float wv3 = w[(size_t)h * (IN_DIM * OUT_DIM) + i * OUT_DIM + o + 3];
        #pragma unroll
        for (int j = 0; j < 4; j++) {
            float xv = xs[(ty * 4 + j) * IN_DIM + i];
            acc[j][0] = fmaf(xv, wv0, acc[j][0]);
            acc[j][1] = fmaf(xv, wv1, acc[j][1]);
            acc[j][2] = fmaf(xv, wv2, acc[j][2]);
            acc[j][3] = fmaf(xv, wv3, acc[j][3]);
        }
    }
    #pragma unroll
    for (int j = 0; j < 4; j++) {
        int n = row0 + ty * 4 + j;
        if (n < n_nodes) {
            float4 v = make_float4(acc[j][0], acc[j][1], acc[j][2], acc[j][3]);
            *(float4*)&g_Wh[(size_t)n * WH_COLS + tx * 4] = v;
        }
    }
}

// ---------------- K1b: per-node attention scalars ----------------
// s_src[n,h] = <Wh[n,h,:], attn[h,0:32]>,  s_dst[n,h] = <Wh[n,h,:], attn[h,32:64]>
__global__ void __launch_bounds__(256) k_svals(const float* __restrict__ attn, int n_nodes) {
    int gw   = (blockIdx.x * blockDim.x + threadIdx.x) >> 5;
    int lane = threadIdx.x & 31;
    if (gw >= n_nodes) return;
    #pragma unroll
    for (int h = 0; h < N_HEADS; h++) {
        float as = attn[h * 2 * OUT_DIM + lane];
        float ad = attn[h * 2 * OUT_DIM + OUT_DIM + lane];
        float v  = g_Wh[(size_t)gw * WH_COLS + h * OUT_DIM + lane];
        float r1 = v * as, r2 = v * ad;
        #pragma unroll
        for (int o = 16; o; o >>= 1) {
            r1 += __shfl_xor_sync(0xffffffffu, r1, o);
            r2 += __shfl_xor_sync(0xffffffffu, r2, o);
        }
        if (lane == 0) {
            g_ssrc[gw * N_HEADS + h] = r1;
            g_sdst[gw * N_HEADS + h] = r2;
        }
    }
}

// ---------------- K2: degree histogram by dst (edge_index is INT32) --------
__global__ void k_hist(const int2* __restrict__ ei, int n_edges, int n_nodes) {
    int e = blockIdx.x * blockDim.x + threadIdx.x;
    if (e < n_edges) {
        int d = ei[e].y;
        if ((unsigned)d < (unsigned)n_nodes) atomicAdd(&g_deg[d], 1);
    }
}

// ---------------- K3: single-block exclusive scan (50k elems) ----------------
__global__ void k_scan(int n_nodes) {
    __shared__ int tmp[1024];
    __shared__ int s_carry;
    int tid = threadIdx.x;
    if (tid == 0) s_carry = 0;
    __syncthreads();
    for (int base = 0; base < n_nodes; base += 1024) {
        int i = base + tid;
        int v = (i < n_nodes) ? g_deg[i] : 0;
        tmp[tid] = v;
        __syncthreads();
        int xv = v;
        for (int ofs = 1; ofs < 1024; ofs <<= 1) {
            int t = (tid >= ofs) ? tmp[tid - ofs] : 0;
            __syncthreads();
            xv += t;
            tmp[tid] = xv;
            __syncthreads();
        }
        int excl  = xv - v;
        int carry = s_carry;
        if (i < n_nodes) {
            g_off[i] = carry + excl;
            g_cur[i] = carry + excl;
        }
        __syncthreads();
        if (tid == 1023) s_carry = carry + xv;
        __syncthreads();
    }
    if (tid == 0) g_off[n_nodes] = s_carry;
}

// ---------------- K4: scatter edges into CSR (by dst) ----------------
__global__ void k_scatter(const int2* __restrict__ ei, int n_edges, int n_nodes) {
    int e = blockIdx.x * blockDim.x + threadIdx.x;
    if (e < n_edges) {
        int2 p = ei[e];
        if ((unsigned)p.y < (unsigned)n_nodes && (unsigned)p.x < (unsigned)n_nodes) {
            int pos = atomicAdd(&g_cur[p.y], 1);
            if ((unsigned)pos < (unsigned)N_EDGES_MAX) g_csr_src[pos] = p.x;
        }
    }
}

// ---------------- K5: per-(dst,head) softmax + aggregation ----------------
// One warp per (node, head). No atomics: warp owns the segment.
__global__ void __launch_bounds__(256) k_agg(float* __restrict__ out_h, int n_nodes) {
    int gw   = (blockIdx.x * blockDim.x + threadIdx.x) >> 5;
    int lane = threadIdx.x & 31;
    int n = gw >> 2;
    int h = gw & 3;
    if (n >= n_nodes) return;

    int beg = g_off[n], end = g_off[n + 1];
    float sdst = g_sdst[n * N_HEADS + h];

    // pass 1: max
    float m = -3.402823466e38f;
    for (int j = beg + lane; j < end; j += 32) {
        int s   = g_csr_src[j];
        float e = g_ssrc[s * N_HEADS + h] + sdst;
        e = (e > 0.f) ? e : 0.2f * e;
        m = fmaxf(m, e);
    }
    #pragma unroll
    for (int o = 16; o; o >>= 1) m = fmaxf(m, __shfl_xor_sync(0xffffffffu, m, o));

    // pass 2: exp-sum + weighted gather-accumulate
    float ssum = 0.f, acc = 0.f;
    for (int base = beg; base < end; base += 32) {
        int j = base + lane;
        int s = 0; float a = 0.f;
        if (j < end) {
            s = g_csr_src[j];
            float e = g_ssrc[s * N_HEADS + h] + sdst;
            e = (e > 0.f) ? e : 0.2f * e;
            a = __expf(e - m);
            ssum += a;
        }
        int cnt = min(32, end - base);
        for (int k = 0; k < cnt; k++) {
            int   sk = __shfl_sync(0xffffffffu, s, k);
            float ak = __shfl_sync(0xffffffffu, a, k);
            acc = fmaf(ak, g_Wh[(size_t)sk * WH_COLS + h * OUT_DIM + lane], acc);
        }
    }
    #pragma unroll
    for (int o = 16; o; o >>= 1) ssum += __shfl_xor_sync(0xffffffffu, ssum, o);

    out_h[(size_t)n * WH_COLS + h * OUT_DIM + lane] = acc / (ssum + 1e-9f);
    if (lane == 0) {
        g_max[n * N_HEADS + h] = m;
        g_sum[n * N_HEADS + h] = ssum;
    }
}

// ---------------- K6: alpha in original edge order --------
__global__ void __launch_bounds__(256) k_alpha(const int2* __restrict__ ei,
                                               float* __restrict__ alpha_out,
                                               int n_edges, int n_nodes) {
    int e = blockIdx.x * blockDim.x + threadIdx.x;
    if (e >= n_edges) return;
    int2 p = ei[e];
    if ((unsigned)p.x >= (unsigned)n_nodes || (unsigned)p.y >= (unsigned)n_nodes) return;
    float4 ss = *(const float4*)&g_ssrc[p.x * 4];
    float4 sd = *(const float4*)&g_sdst[p.y * 4];
    float4 mx = *(const float4*)&g_max[p.y * 4];
    float4 sm = *(const float4*)&g_sum[p.y * 4];
    float4 o;
    {
        float ev;
        ev = ss.x + sd.x; ev = (ev > 0.f) ? ev : 0.2f * ev; o.x = __expf(ev - mx.x) / (sm.x + 1e-9f);
        ev = ss.y + sd.y; ev = (ev > 0.f) ? ev : 0.2f * ev; o.y = __expf(ev - mx.y) / (sm.y + 1e-9f);
        ev = ss.z + sd.z; ev = (ev > 0.f) ? ev : 0.2f * ev; o.z = __expf(ev - mx.z) / (sm.z + 1e-9f);
        ev = ss.w + sd.w; ev = (ev > 0.f) ? ev : 0.2f * ev; o.w = __expf(ev - mx.w) / (sm.w + 1e-9f);
    }
    float* ap = alpha_out + 4 * (size_t)e;
    ap[0] = o.x; ap[1] = o.y; ap[2] = o.z; ap[3] = o.w;
}

// ---------------- launch ----------------
extern "C" void kernel_launch(void* const* d_in, const int* in_sizes, int n_in,
                              void* d_out, int out_size) {
    // Identify inputs robustly by element count (all four are distinct):
    //   x: N*128 = 6,400,000   edge_index: E*2 = 3,200,000 (int32 — JAX x64 disabled)
    //   weight: 4*128*32 = 16,384   attn: 4*64 = 256
    const float* x    = nullptr;
    const int2*  ei   = nullptr;
    const float* w    = nullptr;
    const float* attn = nullptr;
    int x_sz = 0, e_sz = 0;
    for (int i = 0; i < n_in; i++) {
        int sz = in_sizes[i];
        if (sz == N_HEADS * IN_DIM * OUT_DIM)       w    = (const float*)d_in[i];
        else if (sz == N_HEADS * 2 * OUT_DIM)       attn = (const float*)d_in[i];
        else if (sz % IN_DIM == 0 && sz >= 4000000) { x   = (const float*)d_in[i]; x_sz = sz; }
        else                                        { ei  = (const int2*)d_in[i]; e_sz = sz; }
    }
    if (!x || !ei || !w || !attn) {
        x    = (const float*)d_in[0]; x_sz = in_sizes[0];
        ei   = (const int2*)d_in[1];  e_sz = in_sizes[1];
        w    = (const float*)d_in[2];
        attn = (const float*)d_in[3];
    }

    int n_nodes = x_sz / IN_DIM;
    int n_edges = e_sz / 2;
    if (n_nodes > N_NODES_MAX) n_nodes = N_NODES_MAX;
    if (n_edges > N_EDGES_MAX) n_edges = N_EDGES_MAX;

    float* out_h     = (float*)d_out;
    float* out_alpha = (float*)d_out + (size_t)n_nodes * WH_COLS;
    bool   has_alpha = (size_t)out_size >= (size_t)n_nodes * WH_COLS + (size_t)n_edges * N_HEADS;

    int eb = (n_edges + 255) / 256;

    k_zero   <<<(n_nodes + 255) / 256, 256>>>(n_nodes);
    k_wh     <<<(n_nodes + 31) / 32, 256>>>(x, w, n_nodes);
    k_svals  <<<(n_nodes * 32 + 255) / 256, 256>>>(attn, n_nodes);
    k_hist   <<<eb, 256>>>(ei, n_edges, n_nodes);
    k_scan   <<<1, 1024>>>(n_nodes);
    k_scatter<<<eb, 256>>>(ei, n_edges, n_nodes);
    k_agg    <<<(n_nodes * N_HEADS * 32 + 255) / 256, 256>>>(out_h, n_nodes);
    if (has_alpha)
        k_alpha <<<eb, 256>>>(ei, out_alpha, n_edges, n_nodes);
}

// round 9
// speedup vs baseline: 2.3143x; 2.3143x over previous
#include <cuda_runtime.h>
#include <cuda_bf16.h>

#define N_NODES_MAX 50000
#define N_EDGES_MAX 1600000
#define IN_DIM 128
#define OUT_DIM 32
#define N_HEADS 4
#define WH_COLS (N_HEADS * OUT_DIM)   // 128
#define NEG_BIG 3.402823466e38f

// ---------------- scratch (static device memory; no allocs) ----------------
__device__ __align__(16) float g_Wh[N_NODES_MAX * WH_COLS];        // 25.6 MB
__device__ __align__(16) float g_ssrc[N_NODES_MAX * N_HEADS];      // 0.8 MB
__device__ __align__(16) float g_sdst[N_NODES_MAX * N_HEADS];      // 0.8 MB
__device__ __align__(16) float g_max[N_NODES_MAX * N_HEADS];
__device__ __align__(16) float g_sum[N_NODES_MAX * N_HEADS];
__device__ int   g_deg[N_NODES_MAX];
__device__ int   g_off[N_NODES_MAX + 1];
__device__ int   g_cur[N_NODES_MAX];
__device__ int   g_csr_src[N_EDGES_MAX];                           // 6.4 MB

// ---------------- K0: zero degree histogram ----------------
__global__ void k_zero(int n_nodes) {
    int i = blockIdx.x * blockDim.x + threadIdx.x;
    if (i < n_nodes) g_deg[i] = 0;
}

// ---------------- K1: Wh = x @ W  (fused 128x128 GEMM) ----------
__global__ void __launch_bounds__(256) k_wh(const float* __restrict__ x,
                                            const float* __restrict__ w,
                                            int n_nodes) {
    __shared__ __align__(16) float xs[32 * IN_DIM];   // 16 KB
    int tid  = threadIdx.x;
    int row0 = blockIdx.x * 32;

    // stage 32 x-rows via float4 (x base is 256B-aligned)
    float4* xs4 = (float4*)xs;
    const float4* x4 = (const float4*)x;
    for (int idx = tid; idx < 32 * (IN_DIM / 4); idx += 256) {
        int r = idx >> 5, i = idx & 31;
        int n = row0 + r;
        xs4[idx] = (n < n_nodes) ? x4[(size_t)n * (IN_DIM / 4) + i]
                                 : make_float4(0.f, 0.f, 0.f, 0.f);
    }
    __syncthreads();

    int tx = tid & 31;   // col group: cols [4*tx, 4*tx+4)
    int ty = tid >> 5;   // row group: rows [4*ty, 4*ty+4)

    int c = tx * 4;
    int h = c >> 5, o = c & 31;   // 4 consecutive cols stay within one head
    const float* wp = w + (size_t)h * (IN_DIM * OUT_DIM) + o;

    float acc[4][4] = {};
    #pragma unroll 8
    for (int i = 0; i < IN_DIM; i++) {
        const float4 wv = *(const float4*)(wp + i * OUT_DIM);   // 16B-aligned (o mult of 4)
        #pragma unroll
        for (int j = 0; j < 4; j++) {
            float xv = xs[(ty * 4 + j) * IN_DIM + i];
            acc[j][0] = fmaf(xv, wv.x, acc[j][0]);
            acc[j][1] = fmaf(xv, wv.y, acc[j][1]);
            acc[j][2] = fmaf(xv, wv.z, acc[j][2]);
            acc[j][3] = fmaf(xv, wv.w, acc[j][3]);
        }
    }
    #pragma unroll
    for (int j = 0; j < 4; j++) {
        int n = row0 + ty * 4 + j;
        if (n < n_nodes) {
            float4 v = make_float4(acc[j][0], acc[j][1], acc[j][2], acc[j][3]);
            *(float4*)&g_Wh[(size_t)n * WH_COLS + tx * 4] = v;
        }
    }
}

// ---------------- K1b: per-node attention scalars ----------------
__global__ void __launch_bounds__(256) k_svals(const float* __restrict__ attn, int n_nodes) {
    int gw   = (blockIdx.x * blockDim.x + threadIdx.x) >> 5;
    int lane = threadIdx.x & 31;
    if (gw >= n_nodes) return;
    #pragma unroll
    for (int h = 0; h < N_HEADS; h++) {
        float as = attn[h * 2 * OUT_DIM + lane];
        float ad = attn[h * 2 * OUT_DIM + OUT_DIM + lane];
        float v  = g_Wh[(size_t)gw * WH_COLS + h * OUT_DIM + lane];
        float r1 = v * as, r2 = v * ad;
        #pragma unroll
        for (int o = 16; o; o >>= 1) {
            r1 += __shfl_xor_sync(0xffffffffu, r1, o);
            r2 += __shfl_xor_sync(0xffffffffu, r2, o);
        }
        if (lane == 0) {
            g_ssrc[gw * N_HEADS + h] = r1;
            g_sdst[gw * N_HEADS + h] = r2;
        }
    }
}

// ---------------- K2: degree histogram by dst (edge_index is INT32) --------
__global__ void k_hist(const int2* __restrict__ ei, int n_edges, int n_nodes) {
    int e = blockIdx.x * blockDim.x + threadIdx.x;
    if (e < n_edges) {
        int d = ei[e].y;
        if ((unsigned)d < (unsigned)n_nodes) atomicAdd(&g_deg[d], 1);
    }
}

// ---------------- K3: single-block shfl scan (50k elems) ----------------
__global__ void k_scan(int n_nodes) {
    __shared__ int wtot[32];
    __shared__ int s_carry;
    int tid = threadIdx.x, lane = tid & 31, wid = tid >> 5;
    if (tid == 0) s_carry = 0;
    __syncthreads();
    for (int base = 0; base < n_nodes; base += 1024) {
        int i = base + tid;
        int v = (i < n_nodes) ? g_deg[i] : 0;
        int inc = v;
        #pragma unroll
        for (int o = 1; o < 32; o <<= 1) {
            int t = __shfl_up_sync(0xffffffffu, inc, o);
            if (lane >= o) inc += t;
        }
        if (lane == 31) wtot[wid] = inc;
        __syncthreads();
        if (wid == 0) {
            int wv = wtot[lane];
            int wi = wv;
            #pragma unroll
            for (int o = 1; o < 32; o <<= 1) {
                int t = __shfl_up_sync(0xffffffffu, wi, o);
                if (lane >= o) wi += t;
            }
            wtot[lane] = wi - wv;   // exclusive prefix of warp totals
        }
        __syncthreads();
        int carry = s_carry;
        int excl  = carry + wtot[wid] + inc - v;
        if (i < n_nodes) { g_off[i] = excl; g_cur[i] = excl; }
        __syncthreads();
        if (tid == 1023) s_carry = carry + wtot[31] + inc;
        __syncthreads();
    }
    if (tid == 0) g_off[n_nodes] = s_carry;
}

// ---------------- K4: scatter edges into CSR (by dst) ----------------
__global__ void k_scatter(const int2* __restrict__ ei, int n_edges, int n_nodes) {
    int e = blockIdx.x * blockDim.x + threadIdx.x;
    if (e < n_edges) {
        int2 p = ei[e];
        if ((unsigned)p.y < (unsigned)n_nodes && (unsigned)p.x < (unsigned)n_nodes) {
            int pos = atomicAdd(&g_cur[p.y], 1);
            if ((unsigned)pos < (unsigned)N_EDGES_MAX) g_csr_src[pos] = p.x;
        }
    }
}

// ---------------- K5: one warp per node, 4 heads, online softmax ----------
// Lane owns output cols [4*lane, 4*lane+4) (head = lane>>3). Single pass over
// the segment: running max (per head, warp-uniform) with rescale; aggregation
// does one LDG.128 of the Wh row per edge.
__global__ void __launch_bounds__(256) k_agg(float* __restrict__ out_h, int n_nodes) {
    __shared__ __align__(16) float sh_a[8][32][4];
    __shared__ int sh_s[8][32];

    int warp = threadIdx.x >> 5;
    int lane = threadIdx.x & 31;
    int n = blockIdx.x * 8 + warp;
    if (n >= n_nodes) return;

    int beg = g_off[n], end = g_off[n + 1];
    const float4 sdst = *(const float4*)&g_sdst[n * 4];
    int myh = lane >> 3;

    float4 m    = make_float4(-NEG_BIG, -NEG_BIG, -NEG_BIG, -NEG_BIG);
    float4 ssum = make_float4(0.f, 0.f, 0.f, 0.f);
    float4 acc  = make_float4(0.f, 0.f, 0.f, 0.f);

    for (int base = beg; base < end; base += 32) {
        int j = base + lane;
        bool valid = j < end;
        int s = valid ? g_csr_src[j] : 0;
        float4 e;
        if (valid) {
            float4 ss = *(const float4*)&g_ssrc[s * 4];
            e.x = ss.x + sdst.x; e.x = (e.x > 0.f) ? e.x : 0.2f * e.x;
            e.y = ss.y + sdst.y; e.y = (e.y > 0.f) ? e.y : 0.2f * e.y;
            e.z = ss.z + sdst.z; e.z = (e.z > 0.f) ? e.z : 0.2f * e.z;
            e.w = ss.w + sdst.w; e.w = (e.w > 0.f) ? e.w : 0.2f * e.w;
        } else {
            e = make_float4(-NEG_BIG, -NEG_BIG, -NEG_BIG, -NEG_BIG);
        }
        // warp-wide max per head
        float4 bm = e;
        #pragma unroll
        for (int o = 16; o; o >>= 1) {
            bm.x = fmaxf(bm.x, __shfl_xor_sync(0xffffffffu, bm.x, o));
            bm.y = fmaxf(bm.y, __shfl_xor_sync(0xffffffffu, bm.y, o));
            bm.z = fmaxf(bm.z, __shfl_xor_sync(0xffffffffu, bm.z, o));
            bm.w = fmaxf(bm.w, __shfl_xor_sync(0xffffffffu, bm.w, o));
        }
        float4 mn = make_float4(fmaxf(m.x, bm.x), fmaxf(m.y, bm.y),
                                fmaxf(m.z, bm.z), fmaxf(m.w, bm.w));
        float4 sc = make_float4(__expf(m.x - mn.x), __expf(m.y - mn.y),
                                __expf(m.z - mn.z), __expf(m.w - mn.w));
        m = mn;
        float asc = (myh == 0) ? sc.x : (myh == 1) ? sc.y : (myh == 2) ? sc.z : sc.w;
        acc.x *= asc; acc.y *= asc; acc.z *= asc; acc.w *= asc;
        ssum.x *= sc.x; ssum.y *= sc.y; ssum.z *= sc.z; ssum.w *= sc.w;

        float4 a;
        a.x = __expf(e.x - mn.x);   // invalid lanes: exp(-big) -> 0
        a.y = __expf(e.y - mn.y);
        a.z = __expf(e.z - mn.z);
        a.w = __expf(e.w - mn.w);
        ssum.x += a.x; ssum.y += a.y; ssum.z += a.z; ssum.w += a.w;

        *(float4*)&sh_a[warp][lane][0] = a;
        sh_s[warp][lane] = s;
        __syncwarp();

        int cnt = min(32, end - base);
        for (int k = 0; k < cnt; k++) {
            int   sk = sh_s[warp][k];
            float ak = sh_a[warp][k][myh];
            float4 wv = *(const float4*)&g_Wh[(size_t)sk * WH_COLS + lane * 4];
            acc.x = fmaf(ak, wv.x, acc.x);
            acc.y = fmaf(ak, wv.y, acc.y);
            acc.z = fmaf(ak, wv.z, acc.z);
            acc.w = fmaf(ak, wv.w, acc.w);
        }
        __syncwarp();
    }

    // reduce ssum per head across warp
    #pragma unroll
    for (int o = 16; o; o >>= 1) {
        ssum.x += __shfl_xor_sync(0xffffffffu, ssum.x, o);
        ssum.y += __shfl_xor_sync(0xffffffffu, ssum.y, o);
        ssum.z += __shfl_xor_sync(0xffffffffu, ssum.z, o);
        ssum.w += __shfl_xor_sync(0xffffffffu, ssum.w, o);
    }
    float denom = ((myh == 0) ? ssum.x : (myh == 1) ? ssum.y
                  : (myh == 2) ? ssum.z : ssum.w) + 1e-9f;
    float inv = 1.0f / denom;
    float4 o4 = make_float4(acc.x * inv, acc.y * inv, acc.z * inv, acc.w * inv);
    *(float4*)&out_h[(size_t)n * WH_COLS + lane * 4] = o4;
    if (lane == 0) {
        *(float4*)&g_max[n * 4] = m;
        *(float4*)&g_sum[n * 4] = ssum;
    }
}

// ---------------- K6: alpha in original edge order --------
__global__ void __launch_bounds__(256) k_alpha(const int2* __restrict__ ei,
                                               float* __restrict__ alpha_out,
                                               int n_edges, int n_nodes) {
    int e = blockIdx.x * blockDim.x + threadIdx.x;
    if (e >= n_edges) return;
    int2 p = ei[e];
    if ((unsigned)p.x >= (unsigned)n_nodes || (unsigned)p.y >= (unsigned)n_nodes) return;
    float4 ss = *(const float4*)&g_ssrc[p.x * 4];
    float4 sd = *(const float4*)&g_sdst[p.y * 4];
    float4 mx = *(const float4*)&g_max[p.y * 4];
    float4 sm = *(const float4*)&g_sum[p.y * 4];
    float4 o;
    {
        float ev;
        ev = ss.x + sd.x; ev = (ev > 0.f) ? ev : 0.2f * ev; o.x = __expf(ev - mx.x) / (sm.x + 1e-9f);
        ev = ss.y + sd.y; ev = (ev > 0.f) ? ev : 0.2f * ev; o.y = __expf(ev - mx.y) / (sm.y + 1e-9f);
        ev = ss.z + sd.z; ev = (ev > 0.f) ? ev : 0.2f * ev; o.z = __expf(ev - mx.z) / (sm.z + 1e-9f);
        ev = ss.w + sd.w; ev = (ev > 0.f) ? ev : 0.2f * ev; o.w = __expf(ev - mx.w) / (sm.w + 1e-9f);
    }
    float* ap = alpha_out + 4 * (size_t)e;
    ap[0] = o.x; ap[1] = o.y; ap[2] = o.z; ap[3] = o.w;
}

// ---------------- launch ----------------
extern "C" void kernel_launch(void* const* d_in, const int* in_sizes, int n_in,
                              void* d_out, int out_size) {
    const float* x    = nullptr;
    const int2*  ei   = nullptr;
    const float* w    = nullptr;
    const float* attn = nullptr;
    int x_sz = 0, e_sz = 0;
    for (int i = 0; i < n_in; i++) {
        int sz = in_sizes[i];
        if (sz == N_HEADS * IN_DIM * OUT_DIM)       w    = (const float*)d_in[i];
        else if (sz == N_HEADS * 2 * OUT_DIM)       attn = (const float*)d_in[i];
        else if (sz % IN_DIM == 0 && sz >= 4000000) { x   = (const float*)d_in[i]; x_sz = sz; }
        else                                        { ei  = (const int2*)d_in[i]; e_sz = sz; }
    }
    if (!x || !ei || !w || !attn) {
        x    = (const float*)d_in[0]; x_sz = in_sizes[0];
        ei   = (const int2*)d_in[1];  e_sz = in_sizes[1];
        w    = (const float*)d_in[2];
        attn = (const float*)d_in[3];
    }

    int n_nodes = x_sz / IN_DIM;
    int n_edges = e_sz / 2;
    if (n_nodes > N_NODES_MAX) n_nodes = N_NODES_MAX;
    if (n_edges > N_EDGES_MAX) n_edges = N_EDGES_MAX;

    float* out_h     = (float*)d_out;
    float* out_alpha = (float*)d_out + (size_t)n_nodes * WH_COLS;
    bool   has_alpha = (size_t)out_size >= (size_t)n_nodes * WH_COLS + (size_t)n_edges * N_HEADS;

    int eb = (n_edges + 255) / 256;

    k_zero   <<<(n_nodes + 255) / 256, 256>>>(n_nodes);
    k_wh     <<<(n_nodes + 31) / 32, 256>>>(x, w, n_nodes);
    k_svals  <<<(n_nodes * 32 + 255) / 256, 256>>>(attn, n_nodes);
    k_hist   <<<eb, 256>>>(ei, n_edges, n_nodes);
    k_scan   <<<1, 1024>>>(n_nodes);
    k_scatter<<<eb, 256>>>(ei, n_edges, n_nodes);
    k_agg    <<<(n_nodes + 7) / 8, 256>>>(out_h, n_nodes);
    if (has_alpha)
        k_alpha <<<eb, 256>>>(ei, out_alpha, n_edges, n_nodes);
}

// round 11
// speedup vs baseline: 2.5710x; 1.1109x over previous
#include <cuda_runtime.h>
#include <cuda_fp16.h>
#include <cuda_bf16.h>

#define N_NODES_MAX 50000
#define N_EDGES_MAX 1600000
#define IN_DIM 128
#define OUT_DIM 32
#define N_HEADS 4
#define WH_COLS (N_HEADS * OUT_DIM)   // 128
#define NEG_BIG 3.402823466e38f

// ---------------- scratch (static device memory; no allocs) ----------------
__device__ __align__(16) __half g_Wh[N_NODES_MAX * WH_COLS];       // 12.8 MB (fp16)
__device__ __align__(16) float g_ssrc[N_NODES_MAX * N_HEADS];      // 0.8 MB
__device__ __align__(16) float g_sdst[N_NODES_MAX * N_HEADS];      // 0.8 MB
__device__ __align__(16) float g_dstinfo[N_NODES_MAX * 8];         // {max[4], inv[4]} per node
__device__ int   g_deg[N_NODES_MAX];
__device__ int   g_off[N_NODES_MAX + 1];
__device__ int   g_cur[N_NODES_MAX];
__device__ int   g_csr_src[N_EDGES_MAX];                           // 6.4 MB

// ---------------- K0: zero degree histogram ----------------
__global__ void k_zero(int n_nodes) {
    int i = blockIdx.x * blockDim.x + threadIdx.x;
    if (i < n_nodes) g_deg[i] = 0;
}

// ---------------- K1: Wh = x @ W (fp32 math, fp16 store) + fused svals ------
// Warp ty owns rows row0+4*ty..+3; lane tx owns cols 4*tx..4*tx+3 (head tx>>3).
__global__ void __launch_bounds__(256) k_wh(const float* __restrict__ x,
                                            const float* __restrict__ w,
                                            const float* __restrict__ attn,
                                            int n_nodes) {
    __shared__ __align__(16) float xs[32 * IN_DIM];   // 16 KB
    int tid  = threadIdx.x;
    int row0 = blockIdx.x * 32;

    float4* xs4 = (float4*)xs;
    const float4* x4 = (const float4*)x;
    for (int idx = tid; idx < 32 * (IN_DIM / 4); idx += 256) {
        int r = idx >> 5, i = idx & 31;
        int n = row0 + r;
        xs4[idx] = (n < n_nodes) ? x4[(size_t)n * (IN_DIM / 4) + i]
                                 : make_float4(0.f, 0.f, 0.f, 0.f);
    }
    __syncthreads();

    int tx = tid & 31;
    int ty = tid >> 5;

    int c = tx * 4;
    int h = c >> 5, o = c & 31;
    const float* wp = w + (size_t)h * (IN_DIM * OUT_DIM) + o;

    float acc[4][4] = {};
    #pragma unroll 8
    for (int i = 0; i < IN_DIM; i++) {
        const float4 wv = *(const float4*)(wp + i * OUT_DIM);
        #pragma unroll
        for (int j = 0; j < 4; j++) {
            float xv = xs[(ty * 4 + j) * IN_DIM + i];
            acc[j][0] = fmaf(xv, wv.x, acc[j][0]);
            acc[j][1] = fmaf(xv, wv.y, acc[j][1]);
            acc[j][2] = fmaf(xv, wv.z, acc[j][2]);
            acc[j][3] = fmaf(xv, wv.w, acc[j][3]);
        }
    }

    // attention vector slices for this lane's 4 columns
    const float4 as = *(const float4*)(attn + h * 2 * OUT_DIM + o);
    const float4 ad = *(const float4*)(attn + h * 2 * OUT_DIM + OUT_DIM + o);

    #pragma unroll
    for (int j = 0; j < 4; j++) {
        int n = row0 + ty * 4 + j;
        if (n < n_nodes) {
            // fp16 store of the 4 owned columns (8B aligned)
            __half2 h0 = __float22half2_rn(make_float2(acc[j][0], acc[j][1]));
            __half2 h1 = __float22half2_rn(make_float2(acc[j][2], acc[j][3]));
            uint2 packed;
            packed.x = *(unsigned*)&h0;
            packed.y = *(unsigned*)&h1;
            *(uint2*)&g_Wh[(size_t)n * WH_COLS + tx * 4] = packed;
        }
        // fused svals: per-head dot with a_src / a_dst (reduce over 8 lanes of this head)
        float r1 = acc[j][0] * as.x + acc[j][1] * as.y + acc[j][2] * as.z + acc[j][3] * as.w;
        float r2 = acc[j][0] * ad.x + acc[j][1] * ad.y + acc[j][2] * ad.z + acc[j][3] * ad.w;
        #pragma unroll
        for (int of = 4; of; of >>= 1) {
            r1 += __shfl_xor_sync(0xffffffffu, r1, of);
            r2 += __shfl_xor_sync(0xffffffffu, r2, of);
        }
        if ((tx & 7) == 0 && n < n_nodes) {
            g_ssrc[n * N_HEADS + h] = r1;
            g_sdst[n * N_HEADS + h] = r2;
        }
    }
}

// ---------------- K2: degree histogram by dst (edge_index is INT32) --------
__global__ void k_hist(const int2* __restrict__ ei, int n_edges, int n_nodes) {
    int e = blockIdx.x * blockDim.x + threadIdx.x;
    if (e < n_edges) {
        int d = ei[e].y;
        if ((unsigned)d < (unsigned)n_nodes) atomicAdd(&g_deg[d], 1);
    }
}

// ---------------- K3: single-block shfl scan (50k elems) ----------------
__global__ void k_scan(int n_nodes) {
    __shared__ int wtot[32];
    __shared__ int s_carry;
    int tid = threadIdx.x, lane = tid & 31, wid = tid >> 5;
    if (tid == 0) s_carry = 0;
    __syncthreads();
    for (int base = 0; base < n_nodes; base += 1024) {
        int i = base + tid;
        int v = (i < n_nodes) ? g_deg[i] : 0;
        int inc = v;
        #pragma unroll
        for (int o = 1; o < 32; o <<= 1) {
            int t = __shfl_up_sync(0xffffffffu, inc, o);
            if (lane >= o) inc += t;
        }
        if (lane == 31) wtot[wid] = inc;
        __syncthreads();
        if (wid == 0) {
            int wv = wtot[lane];
            int wi = wv;
            #pragma unroll
            for (int o = 1; o < 32; o <<= 1) {
                int t = __shfl_up_sync(0xffffffffu, wi, o);
                if (lane >= o) wi += t;
            }
            wtot[lane] = wi - wv;
        }
        __syncthreads();
        int carry = s_carry;
        int excl  = carry + wtot[wid] + inc - v;
        if (i < n_nodes) { g_off[i] = excl; g_cur[i] = excl; }
        __syncthreads();
        if (tid == 1023) s_carry = carry + wtot[31] + inc;
        __syncthreads();
    }
    if (tid == 0) g_off[n_nodes] = s_carry;
}

// ---------------- K4: scatter edges into CSR (by dst) ----------------
__global__ void k_scatter(const int2* __restrict__ ei, int n_edges, int n_nodes) {
    int e = blockIdx.x * blockDim.x + threadIdx.x;
    if (e < n_edges) {
        int2 p = ei[e];
        if ((unsigned)p.y < (unsigned)n_nodes && (unsigned)p.x < (unsigned)n_nodes) {
            int pos = atomicAdd(&g_cur[p.y], 1);
            if ((unsigned)pos < (unsigned)N_EDGES_MAX) g_csr_src[pos] = p.x;
        }
    }
}

// ---------------- K5: one warp per node, 4 heads, online softmax ----------
__global__ void __launch_bounds__(256) k_agg(float* __restrict__ out_h, int n_nodes) {
    __shared__ __align__(16) float sh_a[8][32][4];
    __shared__ int sh_s[8][32];

    int warp = threadIdx.x >> 5;
    int lane = threadIdx.x & 31;
    int n = blockIdx.x * 8 + warp;
    if (n >= n_nodes) return;

    int beg = g_off[n], end = g_off[n + 1];
    const float4 sdst = *(const float4*)&g_sdst[n * 4];
    int myh = lane >> 3;

    float4 m    = make_float4(-NEG_BIG, -NEG_BIG, -NEG_BIG, -NEG_BIG);
    float4 ssum = make_float4(0.f, 0.f, 0.f, 0.f);
    float4 acc  = make_float4(0.f, 0.f, 0.f, 0.f);

    for (int base = beg; base < end; base += 32) {
        int j = base + lane;
        bool valid = j < end;
        int s = valid ? g_csr_src[j] : 0;
        float4 e;
        if (valid) {
            float4 ss = *(const float4*)&g_ssrc[s * 4];
            e.x = ss.x + sdst.x; e.x = (e.x > 0.f) ? e.x : 0.2f * e.x;
            e.y = ss.y + sdst.y; e.y = (e.y > 0.f) ? e.y : 0.2f * e.y;
            e.z = ss.z + sdst.z; e.z = (e.z > 0.f) ? e.z : 0.2f * e.z;
            e.w = ss.w + sdst.w; e.w = (e.w > 0.f) ? e.w : 0.2f * e.w;
        } else {
            e = make_float4(-NEG_BIG, -NEG_BIG, -NEG_BIG, -NEG_BIG);
        }
        float4 bm = e;
        #pragma unroll
        for (int o = 16; o; o >>= 1) {
            bm.x = fmaxf(bm.x, __shfl_xor_sync(0xffffffffu, bm.x, o));
            bm.y = fmaxf(bm.y, __shfl_xor_sync(0xffffffffu, bm.y, o));
            bm.z = fmaxf(bm.z, __shfl_xor_sync(0xffffffffu, bm.z, o));
            bm.w = fmaxf(bm.w, __shfl_xor_sync(0xffffffffu, bm.w, o));
        }
        float4 mn = make_float4(fmaxf(m.x, bm.x), fmaxf(m.y, bm.y),
                                fmaxf(m.z, bm.z), fmaxf(m.w, bm.w));
        float4 sc = make_float4(__expf(m.x - mn.x), __expf(m.y - mn.y),
                                __expf(m.z - mn.z), __expf(m.w - mn.w));
        m = mn;
        float asc = (myh == 0) ? sc.x : (myh == 1) ? sc.y : (myh == 2) ? sc.z : sc.w;
        acc.x *= asc; acc.y *= asc; acc.z *= asc; acc.w *= asc;
        ssum.x *= sc.x; ssum.y *= sc.y; ssum.z *= sc.z; ssum.w *= sc.w;

        float4 a;
        a.x = __expf(e.x - mn.x);
        a.y = __expf(e.y - mn.y);
        a.z = __expf(e.z - mn.z);
        a.w = __expf(e.w - mn.w);
        ssum.x += a.x; ssum.y += a.y; ssum.z += a.z; ssum.w += a.w;

        *(float4*)&sh_a[warp][lane][0] = a;
        sh_s[warp][lane] = s;
        __syncwarp();

        int cnt = min(32, end - base);
        for (int k = 0; k < cnt; k++) {
            int   sk = sh_s[warp][k];
            float ak = sh_a[warp][k][myh];
            uint2 raw = *(const uint2*)&g_Wh[(size_t)sk * WH_COLS + lane * 4];
            float2 f0 = __half22float2(*(__half2*)&raw.x);
            float2 f1 = __half22float2(*(__half2*)&raw.y);
            acc.x = fmaf(ak, f0.x, acc.x);
            acc.y = fmaf(ak, f0.y, acc.y);
            acc.z = fmaf(ak, f1.x, acc.z);
            acc.w = fmaf(ak, f1.y, acc.w);
        }
        __syncwarp();
    }

    #pragma unroll
    for (int o = 16; o; o >>= 1) {
        ssum.x += __shfl_xor_sync(0xffffffffu, ssum.x, o);
        ssum.y += __shfl_xor_sync(0xffffffffu, ssum.y, o);
        ssum.z += __shfl_xor_sync(0xffffffffu, ssum.z, o);
        ssum.w += __shfl_xor_sync(0xffffffffu, ssum.w, o);
    }
    float denom = ((myh == 0) ? ssum.x : (myh == 1) ? ssum.y
                  : (myh == 2) ? ssum.z : ssum.w) + 1e-9f;
    float inv = 1.0f / denom;
    float4 o4 = make_float4(acc.x * inv, acc.y * inv, acc.z * inv, acc.w * inv);
    *(float4*)&out_h[(size_t)n * WH_COLS + lane * 4] = o4;
    if (lane == 0) {
        float4 invs = make_float4(1.f / (ssum.x + 1e-9f), 1.f / (ssum.y + 1e-9f),
                                  1.f / (ssum.z + 1e-9f), 1.f / (ssum.w + 1e-9f));
        *(float4*)&g_dstinfo[n * 8]     = m;
        *(float4*)&g_dstinfo[n * 8 + 4] = invs;
    }
}

// ---------------- K6: alpha in original edge order --------
__global__ void __launch_bounds__(256) k_alpha(const int2* __restrict__ ei,
                                               float* __restrict__ alpha_out,
                                               int n_edges, int n_nodes) {
    int e = blockIdx.x * blockDim.x + threadIdx.x;
    if (e >= n_edges) return;
    int2 p = ei[e];
    if ((unsigned)p.x >= (unsigned)n_nodes || (unsigned)p.y >= (unsigned)n_nodes) return;
    float4 ss = *(const float4*)&g_ssrc[p.x * 4];
    float4 sd = *(const float4*)&g_sdst[p.y * 4];
    float4 mx = *(const float4*)&g_dstinfo[p.y * 8];
    float4 iv = *(const float4*)&g_dstinfo[p.y * 8 + 4];
    float4 o;
    {
        float ev;
        ev = ss.x + sd.x; ev = (ev > 0.f) ? ev : 0.2f * ev; o.x = __expf(ev - mx.x) * iv.x;
        ev = ss.y + sd.y; ev = (ev > 0.f) ? ev : 0.2f * ev; o.y = __expf(ev - mx.y) * iv.y;
        ev = ss.z + sd.z; ev = (ev > 0.f) ? ev : 0.2f * ev; o.z = __expf(ev - mx.z) * iv.z;
        ev = ss.w + sd.w; ev = (ev > 0.f) ? ev : 0.2f * ev; o.w = __expf(ev - mx.w) * iv.w;
    }
    float* ap = alpha_out + 4 * (size_t)e;
    ap[0] = o.x; ap[1] = o.y; ap[2] = o.z; ap[3] = o.w;
}

// ---------------- launch ----------------
extern "C" void kernel_launch(void* const* d_in, const int* in_sizes, int n_in,
                              void* d_out, int out_size) {
    const float* x    = nullptr;
    const int2*  ei   = nullptr;
    const float* w    = nullptr;
    const float* attn = nullptr;
    int x_sz = 0, e_sz = 0;
    for (int i = 0; i < n_in; i++) {
        int sz = in_sizes[i];
        if (sz == N_HEADS * IN_DIM * OUT_DIM)       w    = (const float*)d_in[i];
        else if (sz == N_HEADS * 2 * OUT_DIM)       attn = (const float*)d_in[i];
        else if (sz % IN_DIM == 0 && sz >= 4000000) { x   = (const float*)d_in[i]; x_sz = sz; }
        else                                        { ei  = (const int2*)d_in[i]; e_sz = sz; }
    }
    if (!x || !ei || !w || !attn) {
        x    = (const float*)d_in[0]; x_sz = in_sizes[0];
        ei   = (const int2*)d_in[1];  e_sz = in_sizes[1];
        w    = (const float*)d_in[2];
        attn = (const float*)d_in[3];
    }

    int n_nodes = x_sz / IN_DIM;
    int n_edges = e_sz / 2;
    if (n_nodes > N_NODES_MAX) n_nodes = N_NODES_MAX;
    if (n_edges > N_EDGES_MAX) n_edges = N_EDGES_MAX;

    float* out_h     = (float*)d_out;
    float* out_alpha = (float*)d_out + (size_t)n_nodes * WH_COLS;
    bool   has_alpha = (size_t)out_size >= (size_t)n_nodes * WH_COLS + (size_t)n_edges * N_HEADS;

    int eb = (n_edges + 255) / 256;

    k_zero   <<<(n_nodes + 255) / 256, 256>>>(n_nodes);
    k_wh     <<<(n_nodes + 31) / 32, 256>>>(x, w, attn, n_nodes);
    k_hist   <<<eb, 256>>>(ei, n_edges, n_nodes);
    k_scan   <<<1, 1024>>>(n_nodes);
    k_scatter<<<eb, 256>>>(ei, n_edges, n_nodes);
    k_agg    <<<(n_nodes + 7) / 8, 256>>>(out_h, n_nodes);
    if (has_alpha)
        k_alpha <<<eb, 256>>>(ei, out_alpha, n_edges, n_nodes);
}

// round 15
// speedup vs baseline: 2.9930x; 1.1641x over previous
#include <cuda_runtime.h>
#include <cuda_fp16.h>
#include <cuda_bf16.h>

#define N_NODES_MAX 50000
#define N_EDGES_MAX 1600000
#define IN_DIM 128
#define OUT_DIM 32
#define N_HEADS 4
#define WH_COLS (N_HEADS * OUT_DIM)   // 128
#define NEG_BIG 3.402823466e38f
#define SCAN_BLK 1024
#define N_SCAN_BLKS ((N_NODES_MAX + SCAN_BLK - 1) / SCAN_BLK)   // 49

// ---------------- scratch (static device memory; no allocs) ----------------
__device__ __align__(16) __half g_Wh[N_NODES_MAX * WH_COLS];       // 12.8 MB (fp16)
__device__ __align__(16) float g_ssrc[N_NODES_MAX * N_HEADS];      // 0.8 MB
__device__ __align__(16) float g_sdst[N_NODES_MAX * N_HEADS];      // 0.8 MB
__device__ __align__(16) float g_dstinfo[N_NODES_MAX * 8];         // {max[4], inv[4]} per node
__device__ int   g_deg[N_NODES_MAX];
__device__ int   g_off[N_NODES_MAX + 1];
__device__ int   g_cur[N_NODES_MAX];
__device__ int   g_blk[64];
__device__ int   g_blkoff[64];
__device__ int   g_csr_src[N_EDGES_MAX];                           // 6.4 MB

// ---------------- K0: zero degree histogram ----------------
__global__ void k_zero(int n_nodes) {
    int i = blockIdx.x * blockDim.x + threadIdx.x;
    if (i < n_nodes) g_deg[i] = 0;
}

// ---------------- K1: Wh = x @ W (fp32 math, fp16 store) + fused svals ------
__global__ void __launch_bounds__(256) k_wh(const float* __restrict__ x,
                                            const float* __restrict__ w,
                                            const float* __restrict__ attn,
                                            int n_nodes) {
    __shared__ __align__(16) float xs[32 * IN_DIM];   // 16 KB
    int tid  = threadIdx.x;
    int row0 = blockIdx.x * 32;

    float4* xs4 = (float4*)xs;
    const float4* x4 = (const float4*)x;
    for (int idx = tid; idx < 32 * (IN_DIM / 4); idx += 256) {
        int r = idx >> 5, i = idx & 31;
        int n = row0 + r;
        xs4[idx] = (n < n_nodes) ? x4[(size_t)n * (IN_DIM / 4) + i]
                                 : make_float4(0.f, 0.f, 0.f, 0.f);
    }
    __syncthreads();

    int tx = tid & 31;
    int ty = tid >> 5;

    int c = tx * 4;
    int h = c >> 5, o = c & 31;
    const float* wp = w + (size_t)h * (IN_DIM * OUT_DIM) + o;

    float acc[4][4] = {};
    #pragma unroll 8
    for (int i = 0; i < IN_DIM; i++) {
        const float4 wv = *(const float4*)(wp + i * OUT_DIM);
        #pragma unroll
        for (int j = 0; j < 4; j++) {
            float xv = xs[(ty * 4 + j) * IN_DIM + i];
            acc[j][0] = fmaf(xv, wv.x, acc[j][0]);
            acc[j][1] = fmaf(xv, wv.y, acc[j][1]);
            acc[j][2] = fmaf(xv, wv.z, acc[j][2]);
            acc[j][3] = fmaf(xv, wv.w, acc[j][3]);
        }
    }

    const float4 as = *(const float4*)(attn + h * 2 * OUT_DIM + o);
    const float4 ad = *(const float4*)(attn + h * 2 * OUT_DIM + OUT_DIM + o);

    #pragma unroll
    for (int j = 0; j < 4; j++) {
        int n = row0 + ty * 4 + j;
        if (n < n_nodes) {
            __half2 h0 = __float22half2_rn(make_float2(acc[j][0], acc[j][1]));
            __half2 h1 = __float22half2_rn(make_float2(acc[j][2], acc[j][3]));
            uint2 packed;
            packed.x = *(unsigned*)&h0;
            packed.y = *(unsigned*)&h1;
            *(uint2*)&g_Wh[(size_t)n * WH_COLS + tx * 4] = packed;
        }
        float r1 = acc[j][0] * as.x + acc[j][1] * as.y + acc[j][2] * as.z + acc[j][3] * as.w;
        float r2 = acc[j][0] * ad.x + acc[j][1] * ad.y + acc[j][2] * ad.z + acc[j][3] * ad.w;
        #pragma unroll
        for (int of = 4; of; of >>= 1) {
            r1 += __shfl_xor_sync(0xffffffffu, r1, of);
            r2 += __shfl_xor_sync(0xffffffffu, r2, of);
        }
        if ((tx & 7) == 0 && n < n_nodes) {
            g_ssrc[n * N_HEADS + h] = r1;
            g_sdst[n * N_HEADS + h] = r2;
        }
    }
}

// ---------------- K2: degree histogram by dst (edge_index is INT32) --------
__global__ void k_hist(const int2* __restrict__ ei, int n_edges, int n_nodes) {
    int e = blockIdx.x * blockDim.x + threadIdx.x;
    if (e < n_edges) {
        int d = ei[e].y;
        if ((unsigned)d < (unsigned)n_nodes) atomicAdd(&g_deg[d], 1);
    }
}

// ---------------- K3a: per-block scan of degree array ----------------
__global__ void __launch_bounds__(SCAN_BLK) k_scan1(int n_nodes) {
    __shared__ int wtot[32];
    int tid = threadIdx.x, lane = tid & 31, wid = tid >> 5;
    int i = blockIdx.x * SCAN_BLK + tid;
    int v = (i < n_nodes) ? g_deg[i] : 0;
    int inc = v;
    #pragma unroll
    for (int o = 1; o < 32; o <<= 1) {
        int t = __shfl_up_sync(0xffffffffu, inc, o);
        if (lane >= o) inc += t;
    }
    if (lane == 31) wtot[wid] = inc;
    __syncthreads();
    if (wid == 0) {
        int wv = wtot[lane];
        int wi = wv;
        #pragma unroll
        for (int o = 1; o < 32; o <<= 1) {
            int t = __shfl_up_sync(0xffffffffu, wi, o);
            if (lane >= o) wi += t;
        }
        wtot[lane] = wi - wv;   // exclusive prefix of warp totals
        if (lane == 31) g_blk[blockIdx.x] = wi;   // block total
    }
    __syncthreads();
    if (i < n_nodes) g_off[i] = wtot[wid] + inc - v;   // block-local exclusive
}

// ---------------- K3b: scan the block totals (1 warp covers 64 slots) ------
__global__ void k_scan2(int nb, int n_nodes) {
    int lane = threadIdx.x;   // 32 threads
    int v0 = (lane < nb) ? g_blk[lane] : 0;
    int v1 = (lane + 32 < nb) ? g_blk[lane + 32] : 0;
    int s0 = v0;
    #pragma unroll
    for (int o = 1; o < 32; o <<= 1) {
        int t = __shfl_up_sync(0xffffffffu, s0, o);
        if (lane >= o) s0 += t;
    }
    int tot0 = __shfl_sync(0xffffffffu, s0, 31);
    int s1 = v1;
    #pragma unroll
    for (int o = 1; o < 32; o <<= 1) {
        int t = __shfl_up_sync(0xffffffffu, s1, o);
        if (lane >= o) s1 += t;
    }
    s1 += tot0;
    g_blkoff[lane]      = s0 - v0;
    g_blkoff[lane + 32] = s1 - v1;
    if (lane == ((nb - 1) & 31)) {
        int incl = (nb - 1 < 32) ? s0 : s1;
        // only the thread holding index nb-1 writes (disambiguate halves)
        if ((nb - 1 < 32 && lane == nb - 1) || (nb - 1 >= 32 && lane + 32 == nb - 1))
            g_off[n_nodes] = incl;
    }
}

// ---------------- K3c: add block offsets ----------------
__global__ void __launch_bounds__(SCAN_BLK) k_scan3(int n_nodes) {
    int i = blockIdx.x * SCAN_BLK + threadIdx.x;
    if (i < n_nodes) {
        int v = g_off[i] + g_blkoff[blockIdx.x];
        g_off[i] = v;
        g_cur[i] = v;
    }
}

// ---------------- K4: scatter edges into CSR (by dst) ----------------
__global__ void k_scatter(const int2* __restrict__ ei, int n_edges, int n_nodes) {
    int e = blockIdx.x * blockDim.x + threadIdx.x;
    if (e < n_edges) {
        int2 p = ei[e];
        if ((unsigned)p.y < (unsigned)n_nodes && (unsigned)p.x < (unsigned)n_nodes) {
            int pos = atomicAdd(&g_cur[p.y], 1);
            if ((unsigned)pos < (unsigned)N_EDGES_MAX) g_csr_src[pos] = p.x;
        }
    }
}

// ---------------- K5: one warp per node, 4 heads, online softmax ----------
__global__ void __launch_bounds__(256) k_agg(float* __restrict__ out_h, int n_nodes) {
    __shared__ __align__(16) float sh_a[8][32][4];
    __shared__ int sh_s[8][32];

    int warp = threadIdx.x >> 5;
    int lane = threadIdx.x & 31;
    int n = blockIdx.x * 8 + warp;
    if (n >= n_nodes) return;

    int beg = g_off[n], end = g_off[n + 1];
    const float4 sdst = *(const float4*)&g_sdst[n * 4];
    int myh = lane >> 3;

    float4 m    = make_float4(-NEG_BIG, -NEG_BIG, -NEG_BIG, -NEG_BIG);
    float4 ssum = make_float4(0.f, 0.f, 0.f, 0.f);
    float4 acc  = make_float4(0.f, 0.f, 0.f, 0.f);

    for (int base = beg; base < end; base += 32) {
        int j = base + lane;
        bool valid = j < end;
        int s = valid ? g_csr_src[j] : 0;
        float4 e;
        if (valid) {
            float4 ss = *(const float4*)&g_ssrc[s * 4];
            e.x = ss.x + sdst.x; e.x = (e.x > 0.f) ? e.x : 0.2f * e.x;
            e.y = ss.y + sdst.y; e.y = (e.y > 0.f) ? e.y : 0.2f * e.y;
            e.z = ss.z + sdst.z; e.z = (e.z > 0.f) ? e.z : 0.2f * e.z;
            e.w = ss.w + sdst.w; e.w = (e.w > 0.f) ? e.w : 0.2f * e.w;
        } else {
            e = make_float4(-NEG_BIG, -NEG_BIG, -NEG_BIG, -NEG_BIG);
        }
        float4 bm = e;
        #pragma unroll
        for (int o = 16; o; o >>= 1) {
            bm.x = fmaxf(bm.x, __shfl_xor_sync(0xffffffffu, bm.x, o));
            bm.y = fmaxf(bm.y, __shfl_xor_sync(0xffffffffu, bm.y, o));
            bm.z = fmaxf(bm.z, __shfl_xor_sync(0xffffffffu, bm.z, o));
            bm.w = fmaxf(bm.w, __shfl_xor_sync(0xffffffffu, bm.w, o));
        }
        float4 mn = make_float4(fmaxf(m.x, bm.x), fmaxf(m.y, bm.y),
                                fmaxf(m.z, bm.z), fmaxf(m.w, bm.w));
        float4 sc = make_float4(__expf(m.x - mn.x), __expf(m.y - mn.y),
                                __expf(m.z - mn.z), __expf(m.w - mn.w));
        m = mn;
        float asc = (myh == 0) ? sc.x : (myh == 1) ? sc.y : (myh == 2) ? sc.z : sc.w;
        acc.x *= asc; acc.y *= asc; acc.z *= asc; acc.w *= asc;
        ssum.x *= sc.x; ssum.y *= sc.y; ssum.z *= sc.z; ssum.w *= sc.w;

        float4 a;
        a.x = __expf(e.x - mn.x);
        a.y = __expf(e.y - mn.y);
        a.z = __expf(e.z - mn.z);
        a.w = __expf(e.w - mn.w);
        ssum.x += a.x; ssum.y += a.y; ssum.z += a.z; ssum.w += a.w;

        *(float4*)&sh_a[warp][lane][0] = a;
        sh_s[warp][lane] = s;
        __syncwarp();

        int cnt = min(32, end - base);
        for (int k = 0; k < cnt; k++) {
            int   sk = sh_s[warp][k];
            float ak = sh_a[warp][k][myh];
            uint2 raw = *(const uint2*)&g_Wh[(size_t)sk * WH_COLS + lane * 4];
            float2 f0 = __half22float2(*(__half2*)&raw.x);
            float2 f1 = __half22float2(*(__half2*)&raw.y);
            acc.x = fmaf(ak, f0.x, acc.x);
            acc.y = fmaf(ak, f0.y, acc.y);
            acc.z = fmaf(ak, f1.x, acc.z);
            acc.w = fmaf(ak, f1.y, acc.w);
        }
        __syncwarp();
    }

    #pragma unroll
    for (int o = 16; o; o >>= 1) {
        ssum.x += __shfl_xor_sync(0xffffffffu, ssum.x, o);
        ssum.y += __shfl_xor_sync(0xffffffffu, ssum.y, o);
        ssum.z += __shfl_xor_sync(0xffffffffu, ssum.z, o);
        ssum.w += __shfl_xor_sync(0xffffffffu, ssum.w, o);
    }
    float denom = ((myh == 0) ? ssum.x : (myh == 1) ? ssum.y
                  : (myh == 2) ? ssum.z : ssum.w) + 1e-9f;
    float inv = 1.0f / denom;
    float4 o4 = make_float4(acc.x * inv, acc.y * inv, acc.z * inv, acc.w * inv);
    *(float4*)&out_h[(size_t)n * WH_COLS + lane * 4] = o4;
    if (lane == 0) {
        float4 invs = make_float4(1.f / (ssum.x + 1e-9f), 1.f / (ssum.y + 1e-9f),
                                  1.f / (ssum.z + 1e-9f), 1.f / (ssum.w + 1e-9f));
        *(float4*)&g_dstinfo[n * 8]     = m;
        *(float4*)&g_dstinfo[n * 8 + 4] = invs;
    }
}

// ---------------- K6: alpha in original edge order --------
__global__ void __launch_bounds__(256) k_alpha(const int2* __restrict__ ei,
                                               float* __restrict__ alpha_out,
                                               int n_edges, int n_nodes) {
    int e = blockIdx.x * blockDim.x + threadIdx.x;
    if (e >= n_edges) return;
    int2 p = ei[e];
    if ((unsigned)p.x >= (unsigned)n_nodes || (unsigned)p.y >= (unsigned)n_nodes) return;
    float4 ss = *(const float4*)&g_ssrc[p.x * 4];
    float4 sd = *(const float4*)&g_sdst[p.y * 4];
    float4 mx = *(const float4*)&g_dstinfo[p.y * 8];
    float4 iv = *(const float4*)&g_dstinfo[p.y * 8 + 4];
    float4 o;
    {
        float ev;
        ev = ss.x + sd.x; ev = (ev > 0.f) ? ev : 0.2f * ev; o.x = __expf(ev - mx.x) * iv.x;
        ev = ss.y + sd.y; ev = (ev > 0.f) ? ev : 0.2f * ev; o.y = __expf(ev - mx.y) * iv.y;
        ev = ss.z + sd.z; ev = (ev > 0.f) ? ev : 0.2f * ev; o.z = __expf(ev - mx.z) * iv.z;
        ev = ss.w + sd.w; ev = (ev > 0.f) ? ev : 0.2f * ev; o.w = __expf(ev - mx.w) * iv.w;
    }
    float* ap = alpha_out + 4 * (size_t)e;
    ap[0] = o.x; ap[1] = o.y; ap[2] = o.z; ap[3] = o.w;
}

// ---------------- launch ----------------
extern "C" void kernel_launch(void* const* d_in, const int* in_sizes, int n_in,
                              void* d_out, int out_size) {
    const float* x    = nullptr;
    const int2*  ei   = nullptr;
    const float* w    = nullptr;
    const float* attn = nullptr;
    int x_sz = 0, e_sz = 0;
    for (int i = 0; i < n_in; i++) {
        int sz = in_sizes[i];
        if (sz == N_HEADS * IN_DIM * OUT_DIM)       w    = (const float*)d_in[i];
        else if (sz == N_HEADS * 2 * OUT_DIM)       attn = (const float*)d_in[i];
        else if (sz % IN_DIM == 0 && sz >= 4000000) { x   = (const float*)d_in[i]; x_sz = sz; }
        else                                        { ei  = (const int2*)d_in[i]; e_sz = sz; }
    }
    if (!x || !ei || !w || !attn) {
        x    = (const float*)d_in[0]; x_sz = in_sizes[0];
        ei   = (const int2*)d_in[1];  e_sz = in_sizes[1];
        w    = (const float*)d_in[2];
        attn = (const float*)d_in[3];
    }

    int n_nodes = x_sz / IN_DIM;
    int n_edges = e_sz / 2;
    if (n_nodes > N_NODES_MAX) n_nodes = N_NODES_MAX;
    if (n_edges > N_EDGES_MAX) n_edges = N_EDGES_MAX;

    float* out_h     = (float*)d_out;
    float* out_alpha = (float*)d_out + (size_t)n_nodes * WH_COLS;
    bool   has_alpha = (size_t)out_size >= (size_t)n_nodes * WH_COLS + (size_t)n_edges * N_HEADS;

    int eb = (n_edges + 255) / 256;
    int nb = (n_nodes + SCAN_BLK - 1) / SCAN_BLK;

    k_zero   <<<(n_nodes + 255) / 256, 256>>>(n_nodes);
    k_wh     <<<(n_nodes + 31) / 32, 256>>>(x, w, attn, n_nodes);
    k_hist   <<<eb, 256>>>(ei, n_edges, n_nodes);
    k_scan1  <<<nb, SCAN_BLK>>>(n_nodes);
    k_scan2  <<<1, 32>>>(nb, n_nodes);
    k_scan3  <<<nb, SCAN_BLK>>>(n_nodes);
    k_scatter<<<eb, 256>>>(ei, n_edges, n_nodes);
    k_agg    <<<(n_nodes + 7) / 8, 256>>>(out_h, n_nodes);
    if (has_alpha)
        k_alpha <<<eb, 256>>>(ei, out_alpha, n_edges, n_nodes);
}